// round 4
// baseline (speedup 1.0000x reference)
#include <cuda_runtime.h>
#include <cuda_pipeline.h>
#include <mma.h>
#include <cstdint>

using namespace nvcuda;

namespace {
constexpr int BATCH = 8;
constexpr int CH    = 1024;
constexpr int P     = 48 * 48;     // 2304
constexpr int PD    = 24;
constexpr int PI    = PD * PD;     // 576
constexpr int S     = PI * PI;     // 331776
constexpr float EPS_L2 = 1e-6f;
constexpr float EPS_MM = 1e-5f;
}

__device__ float g_inva[BATCH * P];
__device__ float g_invb[BATCH * P];
__device__ float g_pool[(size_t)BATCH * S];
__device__ float g_x0  [(size_t)BATCH * S];
__device__ float g_y1  [(size_t)BATCH * 10 * S];
__device__ float g_y2  [(size_t)BATCH * 10 * S];
__device__ float g_y3  [(size_t)BATCH * S];
__device__ float g_rmax[BATCH * PI];
__device__ float g_cmax[BATCH * PI];

// ---------------- f32x2 packed helpers ----------------
__device__ __forceinline__ void fma2(unsigned long long& d, unsigned long long a,
                                     unsigned long long b) {
    asm("fma.rn.f32x2 %0, %1, %2, %0;" : "+l"(d) : "l"(a), "l"(b));
}
__device__ __forceinline__ unsigned long long pack2(float lo, float hi) {
    unsigned long long r;
    asm("mov.b64 %0, {%1, %2};" : "=l"(r) : "f"(lo), "f"(hi));
    return r;
}
__device__ __forceinline__ void unpack2(unsigned long long v, float& lo, float& hi) {
    asm("mov.b64 {%0, %1}, %2;" : "=f"(lo), "=f"(hi) : "l"(v));
}

// ---------------- per-position inverse L2 norms ----------------
__global__ void norm_kernel(const float* __restrict__ fa, const float* __restrict__ fb) {
    int idx = blockIdx.x * blockDim.x + threadIdx.x;
    int b = idx / P, p = idx - b * P;
    const float* a  = fa + (size_t)b * CH * P + p;
    const float* bb = fb + (size_t)b * CH * P + p;
    float sa = 0.f, sb = 0.f;
#pragma unroll 8
    for (int c = 0; c < CH; c++) {
        float x = a[(size_t)c * P];  sa = fmaf(x, x, sa);
        float y = bb[(size_t)c * P]; sb = fmaf(y, y, sb);
    }
    g_inva[idx] = rsqrtf(sa + EPS_L2);
    g_invb[idx] = rsqrtf(sb + EPS_L2);
}

__global__ void zero_pool_kernel() {
    size_t i = (size_t)blockIdx.x * blockDim.x + threadIdx.x;
    g_pool[i] = 0.f;
    if (i < BATCH * PI) g_cmax[i] = 0.f;
}
__global__ void zero_cmax_kernel() {
    int i = blockIdx.x * blockDim.x + threadIdx.x;
    if (i < BATCH * PI) g_cmax[i] = 0.f;
}

// ---------------- correlation GEMM (tf32 wmma, 128x256 block) ----------------
// Epilogue: scale by inv-norms only; relu + x/sqrt(x^2+eps) deferred (monotone
// under max) — atomicMax of raw scaled values into zero-initialized g_pool.
__global__ void __launch_bounds__(256)
corr_kernel(const float* __restrict__ fa, const float* __restrict__ fb) {
    extern __shared__ __align__(16) char dsm[];
    float* Asm = reinterpret_cast<float*>(dsm);            // [2][16][132]
    float* Bsm = reinterpret_cast<float*>(dsm + 16896);    // [2][16][264]

    const int b  = blockIdx.z;
    const float* Ag = fa + (size_t)b * CH * P;
    const float* Bg = fb + (size_t)b * CH * P;
    const int m0 = blockIdx.x * 128, n0 = blockIdx.y * 256;
    const int tid = threadIdx.x, wid = tid >> 5, lane = tid & 31;
    const int wm = wid >> 2, wn = wid & 3;   // warp tile 64(m) x 64(n)

    wmma::fragment<wmma::accumulator, 16, 16, 8, float> acc[4][4];
#pragma unroll
    for (int i = 0; i < 4; i++)
#pragma unroll
        for (int j = 0; j < 4; j++) wmma::fill_fragment(acc[i][j], 0.0f);

    auto As = [&](int buf, int r, int c) -> float* { return Asm + (buf * 16 + r) * 132 + c; };
    auto Bs = [&](int buf, int r, int c) -> float* { return Bsm + (buf * 16 + r) * 264 + c; };

    auto load_tile = [&](int kt, int buf) {
        const int k0 = kt * 16;
#pragma unroll
        for (int v = 0; v < 2; v++) {
            int l = v * 256 + tid;
            int r = l >> 5, c = (l & 31) << 2;
            __pipeline_memcpy_async(As(buf, r, c), Ag + (size_t)(k0 + r) * P + m0 + c, 16);
        }
#pragma unroll
        for (int v = 0; v < 4; v++) {
            int l = v * 256 + tid;
            int r = l >> 6, c = (l & 63) << 2;
            __pipeline_memcpy_async(Bs(buf, r, c), Bg + (size_t)(k0 + r) * P + n0 + c, 16);
        }
        __pipeline_commit();
    };

    load_tile(0, 0);
    const int NT = CH / 16;
    for (int kt = 0; kt < NT; kt++) {
        if (kt + 1 < NT) load_tile(kt + 1, (kt + 1) & 1);
        __pipeline_wait_prior((kt + 1 < NT) ? 1 : 0);
        __syncthreads();
        const int buf = kt & 1;
#pragma unroll
        for (int ks = 0; ks < 2; ks++) {
            const int kk = ks * 8;
            wmma::fragment<wmma::matrix_a, 16, 16, 8, wmma::precision::tf32, wmma::col_major> af[4];
            wmma::fragment<wmma::matrix_b, 16, 16, 8, wmma::precision::tf32, wmma::row_major> bf[4];
#pragma unroll
            for (int i = 0; i < 4; i++)
                wmma::load_matrix_sync(af[i], As(buf, kk, wm * 64 + i * 16), 132);
#pragma unroll
            for (int j = 0; j < 4; j++)
                wmma::load_matrix_sync(bf[j], Bs(buf, kk, wn * 64 + j * 16), 264);
#pragma unroll
            for (int i = 0; i < 4; i++)
#pragma unroll
                for (int j = 0; j < 4; j++)
                    wmma::mma_sync(acc[i][j], af[i], bf[j], acc[i][j]);
        }
        __syncthreads();
    }

    // epilogue: reuse As region as per-warp staging
    float* wbuf = Asm + wid * 256;
#pragma unroll 1
    for (int i = 0; i < 4; i++) {
#pragma unroll 1
        for (int j = 0; j < 4; j++) {
            wmma::store_matrix_sync(wbuf, acc[i][j], 16, wmma::mem_row_major);
            __syncwarp();
            const int tm0 = m0 + wm * 64 + i * 16;
            const int tn0 = n0 + wn * 64 + j * 16;
            const int row = lane >> 1;
            const int cb  = (lane & 1) * 8;
            const int p   = tm0 + row;
            const float ia = g_inva[b * P + p];
            float v[8];
#pragma unroll
            for (int c = 0; c < 8; c++) {
                int q = tn0 + cb + c;
                v[c] = wbuf[row * 16 + cb + c] * ia * g_invb[b * P + q];
            }
            float c2[4];
#pragma unroll
            for (int u = 0; u < 4; u++) c2[u] = fmaxf(v[2 * u], v[2 * u + 1]);
#pragma unroll
            for (int u = 0; u < 4; u++)
                c2[u] = fmaxf(c2[u], __shfl_xor_sync(0xffffffffu, c2[u], 2));
            if ((lane & 2) == 0) {
                const int PA = ((p / 48) >> 1) * 24 + ((p % 48) >> 1);
                float* poolb = g_pool + (size_t)b * S + (size_t)PA * PI;
#pragma unroll
                for (int u = 0; u < 4; u++) {
                    int q  = tn0 + cb + 2 * u;
                    int PB = ((q / 48) >> 1) * 24 + ((q % 48) >> 1);
                    atomicMax(reinterpret_cast<int*>(&poolb[PB]), __float_as_int(c2[u]));
                }
            }
            __syncwarp();
        }
    }
}

// ---------------- mutual matching ----------------
__global__ void rowmax_kernel(int which) {
    const float* x = (which == 0) ? g_pool : g_y3;
    int row  = blockIdx.x * 8 + (threadIdx.x >> 5);
    int lane = threadIdx.x & 31;
    const float* xr = x + (size_t)row * PI;
    float m = 0.f;
    for (int j = lane; j < PI; j += 32) m = fmaxf(m, xr[j]);
#pragma unroll
    for (int o = 16; o; o >>= 1) m = fmaxf(m, __shfl_xor_sync(0xffffffffu, m, o));
    if (lane == 0) g_rmax[row] = m;
}

__global__ void colmax_kernel(int which) {  // grid (8,16), 576 thr
    const float* x = (which == 0) ? g_pool : g_y3;
    int b = blockIdx.x, j = threadIdx.x;
    const float* xb = x + (size_t)b * S;
    int i0 = blockIdx.y * 36;
    float m = 0.f;
    for (int i = i0; i < i0 + 36; i++) m = fmaxf(m, xb[(size_t)i * PI + j]);
    atomicMax(reinterpret_cast<int*>(&g_cmax[b * PI + j]), __float_as_int(m));
}

__global__ void mm_apply_kernel(int which, float* __restrict__ outp) {
    int idx = blockIdx.x * blockDim.x + threadIdx.x;
    int b = idx / S, rem = idx - b * S;
    int i = rem / PI, j = rem - i * PI;
    float v  = which ? g_y3[idx] : g_pool[idx];
    float rm = g_rmax[b * PI + i];
    float cm = g_cmax[b * PI + j];
    if (which == 0) {  // deferred x/sqrt(x^2+eps); monotone so maxes transform too
        v  = v  * rsqrtf(v  * v  + EPS_L2);
        rm = rm * rsqrtf(rm * rm + EPS_L2);
        cm = cm * rsqrtf(cm * cm + EPS_L2);
    }
    float* dst = which ? outp : g_x0;
    dst[idx] = v * (v / (rm + EPS_MM)) * (v / (cm + EPS_MM));
}

// ---------------- Conv4d 3^4 SAME, fp32x2 packed FMA, 4 outputs/thread -------
template <int CI, int CO>
__global__ void __launch_bounds__(256)
conv_kernel(const float* __restrict__ x, float* __restrict__ y,
            const float* __restrict__ w, const float* __restrict__ bias) {
    extern __shared__ __align__(16) char dsm[];
    float2* ws2 = reinterpret_cast<float2*>(dsm);  // [81*CI*CO] duplicated pairs
    __shared__ float bs[CO];
    for (int l = threadIdx.x; l < 81 * CI * CO; l += 256) {
        int tap = l / (CI * CO), r = l - tap * (CI * CO);
        int ci = r / CO, co = r - ci * CO;
        float wv = w[(co * CI + ci) * 81 + tap];
        ws2[l] = make_float2(wv, wv);
    }
    if (threadIdx.x < CO) bs[threadIdx.x] = bias[threadIdx.x];
    __syncthreads();

    int g = blockIdx.x * 256 + threadIdx.x;           // [0, BATCH*S/4)
    int b = g / (S / 4), r = g - b * (S / 4);
    int d4b = (r % 6) * 4; int r2 = r / 6;
    int d3 = r2 % 24; r2 /= 24;
    int d2 = r2 % 24; int d1 = r2 / 24;
    int s0 = ((d1 * 24 + d2) * 24 + d3) * 24 + d4b;
    const float* xb = x + (size_t)b * CI * S;

    unsigned long long acc[2][CO];
#pragma unroll
    for (int h = 0; h < 2; h++)
#pragma unroll
        for (int co = 0; co < CO; co++) acc[h][co] = 0ull;

#pragma unroll 1
    for (int t1 = 0; t1 < 3; t1++) {
        int e1 = d1 + t1 - 1; if ((unsigned)e1 >= 24u) continue;
#pragma unroll 1
        for (int t2 = 0; t2 < 3; t2++) {
            int e2 = d2 + t2 - 1; if ((unsigned)e2 >= 24u) continue;
#pragma unroll 1
            for (int t3 = 0; t3 < 3; t3++) {
                int e3 = d3 + t3 - 1; if ((unsigned)e3 >= 24u) continue;
                int spb  = ((e1 * 24 + e2) * 24 + e3) * 24 + d4b;
                int tap3 = ((t1 * 3 + t2) * 3 + t3) * 3;
#pragma unroll
                for (int ci = 0; ci < CI; ci++) {
                    float xv[6];
#pragma unroll
                    for (int u = 0; u < 6; u++) {
                        int e4 = d4b + u - 1;
                        xv[u] = ((unsigned)e4 < 24u) ? xb[(size_t)ci * S + spb + u - 1] : 0.f;
                    }
#pragma unroll
                    for (int t4 = 0; t4 < 3; t4++) {
                        unsigned long long xp0 = pack2(xv[t4],     xv[t4 + 1]);
                        unsigned long long xp1 = pack2(xv[t4 + 2], xv[t4 + 3]);
                        const unsigned long long* wq =
                            reinterpret_cast<const unsigned long long*>(
                                ws2 + ((tap3 + t4) * CI + ci) * CO);
#pragma unroll
                        for (int co = 0; co < CO; co++) {
                            unsigned long long wv = wq[co];
                            fma2(acc[0][co], xp0, wv);
                            fma2(acc[1][co], xp1, wv);
                        }
                    }
                }
            }
        }
    }
#pragma unroll
    for (int co = 0; co < CO; co++) {
        float a0, a1, a2, a3;
        unpack2(acc[0][co], a0, a1);
        unpack2(acc[1][co], a2, a3);
        float bb = bs[co];
        float4 o;
        o.x = fmaxf(a0 + bb, 0.f);
        o.y = fmaxf(a1 + bb, 0.f);
        o.z = fmaxf(a2 + bb, 0.f);
        o.w = fmaxf(a3 + bb, 0.f);
        *reinterpret_cast<float4*>(&y[((size_t)b * CO + co) * S + s0]) = o;
    }
}

extern "C" void kernel_launch(void* const* d_in, const int* in_sizes, int n_in,
                              void* d_out, int out_size) {
    const float* fa = (const float*)d_in[0];
    const float* fb = (const float*)d_in[1];
    const float* w1 = (const float*)d_in[2];
    const float* b1 = (const float*)d_in[3];
    const float* w2 = (const float*)d_in[4];
    const float* b2 = (const float*)d_in[5];
    const float* w3 = (const float*)d_in[6];
    const float* b3 = (const float*)d_in[7];
    float* out = (float*)d_out;

    float *p_x0, *p_y1, *p_y2, *p_y3;
    cudaGetSymbolAddress((void**)&p_x0, g_x0);
    cudaGetSymbolAddress((void**)&p_y1, g_y1);
    cudaGetSymbolAddress((void**)&p_y2, g_y2);
    cudaGetSymbolAddress((void**)&p_y3, g_y3);

    const int CORR_SMEM = 16896 + 33792;   // As + Bs
    cudaFuncSetAttribute(corr_kernel, cudaFuncAttributeMaxDynamicSharedMemorySize, CORR_SMEM);
    cudaFuncSetAttribute(conv_kernel<10, 10>, cudaFuncAttributeMaxDynamicSharedMemorySize,
                         81 * 100 * (int)sizeof(float2));

    const int NS = BATCH * S / 256;      // 10368
    const int NG = BATCH * (S / 4) / 256; // 2592
    norm_kernel<<<BATCH * P / 256, 256>>>(fa, fb);
    zero_pool_kernel<<<NS, 256>>>();
    dim3 cg(18, 9, 8);
    corr_kernel<<<cg, 256, CORR_SMEM>>>(fa, fb);

    rowmax_kernel<<<BATCH * PI / 8, 256>>>(0);
    colmax_kernel<<<dim3(8, 16), PI>>>(0);
    mm_apply_kernel<<<NS, 256>>>(0, nullptr);

    conv_kernel<1, 10><<<NG, 256, 81 * 10 * sizeof(float2)>>>(p_x0, p_y1, w1, b1);
    conv_kernel<10, 10><<<NG, 256, 81 * 100 * sizeof(float2)>>>(p_y1, p_y2, w2, b2);
    conv_kernel<10, 1><<<NG, 256, 81 * 10 * sizeof(float2)>>>(p_y2, p_y3, w3, b3);

    zero_cmax_kernel<<<(BATCH * PI + 255) / 256, 256>>>();
    rowmax_kernel<<<BATCH * PI / 8, 256>>>(1);
    colmax_kernel<<<dim3(8, 16), PI>>>(1);
    mm_apply_kernel<<<NS, 256>>>(1, out);
}

// round 5
// speedup vs baseline: 1.6711x; 1.6711x over previous
#include <cuda_runtime.h>
#include <cuda_pipeline.h>
#include <mma.h>
#include <cstdint>

using namespace nvcuda;

namespace {
constexpr int BATCH = 8;
constexpr int CH    = 1024;
constexpr int P     = 48 * 48;     // 2304
constexpr int PD    = 24;
constexpr int PI    = PD * PD;     // 576
constexpr int S     = PI * PI;     // 331776
constexpr float EPS_L2 = 1e-6f;
constexpr float EPS_MM = 1e-5f;
}

__device__ float g_inva[BATCH * P];
__device__ float g_invb[BATCH * P];
__device__ float g_pool[(size_t)BATCH * S];
__device__ float g_x0  [(size_t)BATCH * S];
__device__ float g_y1  [(size_t)BATCH * 10 * S];
__device__ float g_y2  [(size_t)BATCH * 10 * S];
__device__ float g_y3  [(size_t)BATCH * S];
__device__ float g_rmax[BATCH * PI];
__device__ float g_cmax[BATCH * PI];

// ---------------- f32x2 packed helpers ----------------
__device__ __forceinline__ void fma2(unsigned long long& d, unsigned long long a,
                                     unsigned long long b) {
    asm("fma.rn.f32x2 %0, %1, %2, %0;" : "+l"(d) : "l"(a), "l"(b));
}
__device__ __forceinline__ unsigned long long pack2(float lo, float hi) {
    unsigned long long r;
    asm("mov.b64 %0, {%1, %2};" : "=l"(r) : "f"(lo), "f"(hi));
    return r;
}
__device__ __forceinline__ void unpack2(unsigned long long v, float& lo, float& hi) {
    asm("mov.b64 {%0, %1}, %2;" : "=f"(lo), "=f"(hi) : "l"(v));
}

// ---------------- per-position inverse L2 norms ----------------
__global__ void norm_kernel(const float* __restrict__ fa, const float* __restrict__ fb) {
    int idx = blockIdx.x * blockDim.x + threadIdx.x;
    int b = idx / P, p = idx - b * P;
    const float* a  = fa + (size_t)b * CH * P + p;
    const float* bb = fb + (size_t)b * CH * P + p;
    float sa = 0.f, sb = 0.f;
#pragma unroll 8
    for (int c = 0; c < CH; c++) {
        float x = a[(size_t)c * P];  sa = fmaf(x, x, sa);
        float y = bb[(size_t)c * P]; sb = fmaf(y, y, sb);
    }
    g_inva[idx] = rsqrtf(sa + EPS_L2);
    g_invb[idx] = rsqrtf(sb + EPS_L2);
}

__global__ void zero_pool_kernel() {
    size_t i = (size_t)blockIdx.x * blockDim.x + threadIdx.x;
    g_pool[i] = 0.f;
}
__global__ void zero_cmax_kernel() {
    int i = blockIdx.x * blockDim.x + threadIdx.x;
    if (i < BATCH * PI) g_cmax[i] = 0.f;
}

// ---- correlation GEMM (tf32 wmma, 128x128 block, 64x32 warp tile) ----
// Epilogue: scale by inv-norms only; relu + x/sqrt(x^2+eps) deferred (monotone
// under max, and negatives lose atomicMax vs 0-init => relu preserved).
__global__ void __launch_bounds__(256)
corr_kernel(const float* __restrict__ fa, const float* __restrict__ fb) {
    __shared__ __align__(16) float As[2][16][132];
    __shared__ __align__(16) float Bs[2][16][132];
    __shared__ float wbuf[8][256];

    const int b  = blockIdx.z;
    const float* Ag = fa + (size_t)b * CH * P;
    const float* Bg = fb + (size_t)b * CH * P;
    const int m0 = blockIdx.x * 128, n0 = blockIdx.y * 128;
    const int tid = threadIdx.x, wid = tid >> 5, lane = tid & 31;
    const int wm = wid >> 2, wn = wid & 3;   // 64(m) x 32(n) per warp

    wmma::fragment<wmma::accumulator, 16, 16, 8, float> acc[4][2];
#pragma unroll
    for (int i = 0; i < 4; i++)
#pragma unroll
        for (int j = 0; j < 2; j++) wmma::fill_fragment(acc[i][j], 0.0f);

    auto load_tile = [&](int kt, int buf) {
        const int k0 = kt * 16;
#pragma unroll
        for (int v = 0; v < 2; v++) {
            int l = tid + v * 256;
            int r = l >> 5, c = (l & 31) << 2;
            __pipeline_memcpy_async(&As[buf][r][c], Ag + (size_t)(k0 + r) * P + m0 + c, 16);
            __pipeline_memcpy_async(&Bs[buf][r][c], Bg + (size_t)(k0 + r) * P + n0 + c, 16);
        }
        __pipeline_commit();
    };

    load_tile(0, 0);
    const int NT = CH / 16;
    for (int kt = 0; kt < NT; kt++) {
        if (kt + 1 < NT) load_tile(kt + 1, (kt + 1) & 1);
        __pipeline_wait_prior((kt + 1 < NT) ? 1 : 0);
        __syncthreads();
        const int buf = kt & 1;
#pragma unroll
        for (int ks = 0; ks < 2; ks++) {
            const int kk = ks * 8;
            wmma::fragment<wmma::matrix_a, 16, 16, 8, wmma::precision::tf32, wmma::col_major> af[4];
            wmma::fragment<wmma::matrix_b, 16, 16, 8, wmma::precision::tf32, wmma::row_major> bf[2];
#pragma unroll
            for (int i = 0; i < 4; i++)
                wmma::load_matrix_sync(af[i], &As[buf][kk][wm * 64 + i * 16], 132);
#pragma unroll
            for (int j = 0; j < 2; j++)
                wmma::load_matrix_sync(bf[j], &Bs[buf][kk][wn * 32 + j * 16], 132);
#pragma unroll
            for (int i = 0; i < 4; i++)
#pragma unroll
                for (int j = 0; j < 2; j++)
                    wmma::mma_sync(acc[i][j], af[i], bf[j], acc[i][j]);
        }
        __syncthreads();
    }

#pragma unroll 1
    for (int i = 0; i < 4; i++) {
#pragma unroll 1
        for (int j = 0; j < 2; j++) {
            wmma::store_matrix_sync(&wbuf[wid][0], acc[i][j], 16, wmma::mem_row_major);
            __syncwarp();
            const int tm0 = m0 + wm * 64 + i * 16;
            const int tn0 = n0 + wn * 32 + j * 16;
            const int row = lane >> 1;
            const int cb  = (lane & 1) * 8;
            const int p   = tm0 + row;
            const float ia = g_inva[b * P + p];
            float v[8];
#pragma unroll
            for (int c = 0; c < 8; c++) {
                int q = tn0 + cb + c;
                v[c] = wbuf[wid][row * 16 + cb + c] * ia * g_invb[b * P + q];
            }
            float c2[4];
#pragma unroll
            for (int u = 0; u < 4; u++) c2[u] = fmaxf(v[2 * u], v[2 * u + 1]);
#pragma unroll
            for (int u = 0; u < 4; u++)
                c2[u] = fmaxf(c2[u], __shfl_xor_sync(0xffffffffu, c2[u], 2));
            if ((lane & 2) == 0) {
                const int PA = ((p / 48) >> 1) * 24 + ((p % 48) >> 1);
                float* poolb = g_pool + (size_t)b * S + (size_t)PA * PI;
#pragma unroll
                for (int u = 0; u < 4; u++) {
                    int q  = tn0 + cb + 2 * u;
                    int PB = ((q / 48) >> 1) * 24 + ((q % 48) >> 1);
                    atomicMax(reinterpret_cast<int*>(&poolb[PB]), __float_as_int(c2[u]));
                }
            }
            __syncwarp();
        }
    }
}

// ---------------- mutual matching ----------------
__global__ void rowmax_kernel(int which) {
    const float* x = (which == 0) ? g_pool : g_y3;
    int row  = blockIdx.x * 8 + (threadIdx.x >> 5);
    int lane = threadIdx.x & 31;
    const float* xr = x + (size_t)row * PI;
    float m = 0.f;
    for (int j = lane; j < PI; j += 32) m = fmaxf(m, xr[j]);
#pragma unroll
    for (int o = 16; o; o >>= 1) m = fmaxf(m, __shfl_xor_sync(0xffffffffu, m, o));
    if (lane == 0) g_rmax[row] = m;
}

__global__ void colmax_kernel(int which) {  // grid (8,16), 576 thr
    const float* x = (which == 0) ? g_pool : g_y3;
    int b = blockIdx.x, j = threadIdx.x;
    const float* xb = x + (size_t)b * S;
    int i0 = blockIdx.y * 36;
    float m = 0.f;
    for (int i = i0; i < i0 + 36; i++) m = fmaxf(m, xb[(size_t)i * PI + j]);
    atomicMax(reinterpret_cast<int*>(&g_cmax[b * PI + j]), __float_as_int(m));
}

__global__ void mm_apply_kernel(int which, float* __restrict__ outp) {
    int idx = blockIdx.x * blockDim.x + threadIdx.x;
    int b = idx / S, rem = idx - b * S;
    int i = rem / PI, j = rem - i * PI;
    float v  = which ? g_y3[idx] : g_pool[idx];
    float rm = g_rmax[b * PI + i];
    float cm = g_cmax[b * PI + j];
    if (which == 0) {  // deferred x/sqrt(x^2+eps); monotone so maxes transform too
        v  = v  * rsqrtf(v  * v  + EPS_L2);
        rm = rm * rsqrtf(rm * rm + EPS_L2);
        cm = cm * rsqrtf(cm * cm + EPS_L2);
    }
    float* dst = which ? outp : g_x0;
    dst[idx] = v * (v / (rm + EPS_MM)) * (v / (cm + EPS_MM));
}

// ---------------- Conv4d 3^4 SAME, fp32x2 packed FMA, 4 outputs/thread -------
template <int CI, int CO>
__global__ void __launch_bounds__(256)
conv_kernel(const float* __restrict__ x, float* __restrict__ y,
            const float* __restrict__ w, const float* __restrict__ bias) {
    extern __shared__ __align__(16) char dsm[];
    float2* ws2 = reinterpret_cast<float2*>(dsm);  // duplicated weight pairs
    __shared__ float bs[CO];
    for (int l = threadIdx.x; l < 81 * CI * CO; l += 256) {
        int tap = l / (CI * CO), r = l - tap * (CI * CO);
        int ci = r / CO, co = r - ci * CO;
        float wv = w[(co * CI + ci) * 81 + tap];
        ws2[l] = make_float2(wv, wv);
    }
    if (threadIdx.x < CO) bs[threadIdx.x] = bias[threadIdx.x];
    __syncthreads();

    int g = blockIdx.x * 256 + threadIdx.x;           // [0, BATCH*S/4)
    int b = g / (S / 4), r = g - b * (S / 4);
    int d4b = (r % 6) * 4; int r2 = r / 6;
    int d3 = r2 % 24; r2 /= 24;
    int d2 = r2 % 24; int d1 = r2 / 24;
    int s0 = ((d1 * 24 + d2) * 24 + d3) * 24 + d4b;
    const float* xb = x + (size_t)b * CI * S;

    unsigned long long acc[2][CO];
#pragma unroll
    for (int h = 0; h < 2; h++)
#pragma unroll
        for (int co = 0; co < CO; co++) acc[h][co] = 0ull;

#pragma unroll 1
    for (int t1 = 0; t1 < 3; t1++) {
        int e1 = d1 + t1 - 1; if ((unsigned)e1 >= 24u) continue;
#pragma unroll 1
        for (int t2 = 0; t2 < 3; t2++) {
            int e2 = d2 + t2 - 1; if ((unsigned)e2 >= 24u) continue;
#pragma unroll 1
            for (int t3 = 0; t3 < 3; t3++) {
                int e3 = d3 + t3 - 1; if ((unsigned)e3 >= 24u) continue;
                int spb  = ((e1 * 24 + e2) * 24 + e3) * 24 + d4b;
                int tap3 = ((t1 * 3 + t2) * 3 + t3) * 3;
#pragma unroll
                for (int ci = 0; ci < CI; ci++) {
                    float xv[6];
#pragma unroll
                    for (int u = 0; u < 6; u++) {
                        int e4 = d4b + u - 1;
                        xv[u] = ((unsigned)e4 < 24u) ? xb[(size_t)ci * S + spb + u - 1] : 0.f;
                    }
#pragma unroll
                    for (int t4 = 0; t4 < 3; t4++) {
                        unsigned long long xp0 = pack2(xv[t4],     xv[t4 + 1]);
                        unsigned long long xp1 = pack2(xv[t4 + 2], xv[t4 + 3]);
                        const unsigned long long* wq =
                            reinterpret_cast<const unsigned long long*>(
                                ws2 + ((tap3 + t4) * CI + ci) * CO);
#pragma unroll
                        for (int co = 0; co < CO; co++) {
                            unsigned long long wv = wq[co];
                            fma2(acc[0][co], xp0, wv);
                            fma2(acc[1][co], xp1, wv);
                        }
                    }
                }
            }
        }
    }
#pragma unroll
    for (int co = 0; co < CO; co++) {
        float a0, a1, a2, a3;
        unpack2(acc[0][co], a0, a1);
        unpack2(acc[1][co], a2, a3);
        float bb = bs[co];
        float4 o;
        o.x = fmaxf(a0 + bb, 0.f);
        o.y = fmaxf(a1 + bb, 0.f);
        o.z = fmaxf(a2 + bb, 0.f);
        o.w = fmaxf(a3 + bb, 0.f);
        *reinterpret_cast<float4*>(&y[((size_t)b * CO + co) * S + s0]) = o;
    }
}

extern "C" void kernel_launch(void* const* d_in, const int* in_sizes, int n_in,
                              void* d_out, int out_size) {
    const float* fa = (const float*)d_in[0];
    const float* fb = (const float*)d_in[1];
    const float* w1 = (const float*)d_in[2];
    const float* b1 = (const float*)d_in[3];
    const float* w2 = (const float*)d_in[4];
    const float* b2 = (const float*)d_in[5];
    const float* w3 = (const float*)d_in[6];
    const float* b3 = (const float*)d_in[7];
    float* out = (float*)d_out;

    float *p_x0, *p_y1, *p_y2, *p_y3;
    cudaGetSymbolAddress((void**)&p_x0, g_x0);
    cudaGetSymbolAddress((void**)&p_y1, g_y1);
    cudaGetSymbolAddress((void**)&p_y2, g_y2);
    cudaGetSymbolAddress((void**)&p_y3, g_y3);

    cudaFuncSetAttribute(conv_kernel<10, 10>, cudaFuncAttributeMaxDynamicSharedMemorySize,
                         81 * 100 * (int)sizeof(float2));

    const int NS = BATCH * S / 256;       // 10368
    const int NG = BATCH * (S / 4) / 256; // 2592
    // launch order arranged so corr_kernel is launch #4 (profiler slot)
    norm_kernel<<<BATCH * P / 256, 256>>>(fa, fb);
    zero_pool_kernel<<<NS, 256>>>();
    zero_cmax_kernel<<<(BATCH * PI + 255) / 256, 256>>>();
    dim3 cg(18, 18, 8);
    corr_kernel<<<cg, 256>>>(fa, fb);

    rowmax_kernel<<<BATCH * PI / 8, 256>>>(0);
    colmax_kernel<<<dim3(8, 16), PI>>>(0);
    mm_apply_kernel<<<NS, 256>>>(0, nullptr);

    conv_kernel<1, 10><<<NG, 256, 81 * 10 * sizeof(float2)>>>(p_x0, p_y1, w1, b1);
    conv_kernel<10, 10><<<NG, 256, 81 * 100 * sizeof(float2)>>>(p_y1, p_y2, w2, b2);
    conv_kernel<10, 1><<<NG, 256, 81 * 10 * sizeof(float2)>>>(p_y2, p_y3, w3, b3);

    zero_cmax_kernel<<<(BATCH * PI + 255) / 256, 256>>>();
    rowmax_kernel<<<BATCH * PI / 8, 256>>>(1);
    colmax_kernel<<<dim3(8, 16), PI>>>(1);
    mm_apply_kernel<<<NS, 256>>>(1, out);
}

// round 8
// speedup vs baseline: 1.8187x; 1.0883x over previous
#include <cuda_runtime.h>
#include <cuda_pipeline.h>
#include <cuda_fp16.h>
#include <mma.h>
#include <cstdint>

using namespace nvcuda;

namespace {
constexpr int BATCH = 8;
constexpr int CH    = 1024;
constexpr int P     = 48 * 48;     // 2304
constexpr int PD    = 24;
constexpr int PI    = PD * PD;     // 576
constexpr int S     = PI * PI;     // 331776
constexpr float EPS_L2 = 1e-6f;
constexpr float EPS_MM = 1e-5f;
}

__device__ float  g_inva[BATCH * P];
__device__ float  g_invb[BATCH * P];
__device__ __half g_fah[(size_t)BATCH * CH * P];  // scaled fp16 A, [b][k][p]
__device__ __half g_fbh[(size_t)BATCH * CH * P];  // scaled fp16 B, [b][k][p]
__device__ float  g_pool[(size_t)BATCH * S];
__device__ float  g_x0  [(size_t)BATCH * S];
__device__ float  g_y1  [(size_t)BATCH * 10 * S];
__device__ float  g_y2  [(size_t)BATCH * 10 * S];
__device__ float  g_y3  [(size_t)BATCH * S];
__device__ float  g_rmax[BATCH * PI];
__device__ float  g_cmax[BATCH * PI];

// ---------------- f32x2 packed helpers (convs) ----------------
__device__ __forceinline__ void fma2(unsigned long long& d, unsigned long long a,
                                     unsigned long long b) {
    asm("fma.rn.f32x2 %0, %1, %2, %0;" : "+l"(d) : "l"(a), "l"(b));
}
__device__ __forceinline__ unsigned long long pack2(float lo, float hi) {
    unsigned long long r;
    asm("mov.b64 %0, {%1, %2};" : "=l"(r) : "f"(lo), "f"(hi));
    return r;
}
__device__ __forceinline__ void unpack2(unsigned long long v, float& lo, float& hi) {
    asm("mov.b64 {%0, %1}, %2;" : "=f"(lo), "=f"(hi) : "l"(v));
}

// ---------------- per-position inverse L2 norms ----------------
__global__ void norm_kernel(const float* __restrict__ fa, const float* __restrict__ fb) {
    int idx = blockIdx.x * blockDim.x + threadIdx.x;
    int b = idx / P, p = idx - b * P;
    const float* a  = fa + (size_t)b * CH * P + p;
    const float* bb = fb + (size_t)b * CH * P + p;
    float sa = 0.f, sb = 0.f;
#pragma unroll 8
    for (int c = 0; c < CH; c++) {
        float x = a[(size_t)c * P];  sa = fmaf(x, x, sa);
        float y = bb[(size_t)c * P]; sb = fmaf(y, y, sb);
    }
    g_inva[idx] = rsqrtf(sa + EPS_L2);
    g_invb[idx] = rsqrtf(sb + EPS_L2);
}

__global__ void zero_pool_kernel() {
    size_t i = (size_t)blockIdx.x * blockDim.x + threadIdx.x;
    g_pool[i] = 0.f;
    if (i < BATCH * PI) g_cmax[i] = 0.f;
}
__global__ void zero_cmax_kernel() {
    int i = blockIdx.x * blockDim.x + threadIdx.x;
    if (i < BATCH * PI) g_cmax[i] = 0.f;
}

// ---- scale-by-invnorm + fp16 convert, layout preserved [b][k][p] ----
__global__ void scale_half_kernel(const float* __restrict__ fa,
                                  const float* __restrict__ fb) {
    size_t i4 = (size_t)blockIdx.x * blockDim.x + threadIdx.x;   // 4 elements each
    size_t i  = i4 * 4;
    if (i >= (size_t)BATCH * CH * P) return;
    int b  = (int)(i / ((size_t)CH * P));
    int p  = (int)(i % P);
    const float4 a4 = *reinterpret_cast<const float4*>(fa + i);
    const float4 b4 = *reinterpret_cast<const float4*>(fb + i);
    const float* ia = g_inva + b * P + p;
    const float* ib = g_invb + b * P + p;
    __half2 ha0 = __floats2half2_rn(a4.x * ia[0], a4.y * ia[1]);
    __half2 ha1 = __floats2half2_rn(a4.z * ia[2], a4.w * ia[3]);
    __half2 hb0 = __floats2half2_rn(b4.x * ib[0], b4.y * ib[1]);
    __half2 hb1 = __floats2half2_rn(b4.z * ib[2], b4.w * ib[3]);
    *reinterpret_cast<__half2*>(&g_fah[i])     = ha0;
    *reinterpret_cast<__half2*>(&g_fah[i + 2]) = ha1;
    *reinterpret_cast<__half2*>(&g_fbh[i])     = hb0;
    *reinterpret_cast<__half2*>(&g_fbh[i + 2]) = hb1;
}

// ---- correlation GEMM (fp16 wmma m16n16k16, 128x128 block, 64x32 warp) ----
// Inputs pre-scaled; epilogue = 2x2x2x2 pool via atomicMax (relu via 0-init;
// x/sqrt(x^2+eps) deferred to mm_apply — monotone under max).
__global__ void __launch_bounds__(256)
corr_kernel(const __half* __restrict__ fah, const __half* __restrict__ fbh) {
    __shared__ __align__(16) __half As[2][32][136];
    __shared__ __align__(16) __half Bs[2][32][136];
    __shared__ float wbuf[8][256];

    const int b  = blockIdx.z;
    const __half* Ag = fah + (size_t)b * CH * P;
    const __half* Bg = fbh + (size_t)b * CH * P;
    const int m0 = blockIdx.x * 128, n0 = blockIdx.y * 128;
    const int tid = threadIdx.x, wid = tid >> 5, lane = tid & 31;
    const int wm = wid >> 2, wn = wid & 3;   // 64(m) x 32(n) per warp

    wmma::fragment<wmma::accumulator, 16, 16, 16, float> acc[4][2];
#pragma unroll
    for (int i = 0; i < 4; i++)
#pragma unroll
        for (int j = 0; j < 2; j++) wmma::fill_fragment(acc[i][j], 0.0f);

    auto load_tile = [&](int kt, int buf) {
        const int k0 = kt * 32;
#pragma unroll
        for (int v = 0; v < 2; v++) {
            int l = v * 256 + tid;              // 0..511
            int r = l >> 4, c = (l & 15) * 8;   // row k, 8-half chunk
            __pipeline_memcpy_async(&As[buf][r][c], Ag + (size_t)(k0 + r) * P + m0 + c, 16);
            __pipeline_memcpy_async(&Bs[buf][r][c], Bg + (size_t)(k0 + r) * P + n0 + c, 16);
        }
        __pipeline_commit();
    };

    load_tile(0, 0);
    const int NT = CH / 32;   // 32
    for (int kt = 0; kt < NT; kt++) {
        if (kt + 1 < NT) load_tile(kt + 1, (kt + 1) & 1);
        __pipeline_wait_prior((kt + 1 < NT) ? 1 : 0);
        __syncthreads();
        const int buf = kt & 1;
#pragma unroll
        for (int ks = 0; ks < 2; ks++) {
            const int kk = ks * 16;
            wmma::fragment<wmma::matrix_a, 16, 16, 16, __half, wmma::col_major> af[4];
            wmma::fragment<wmma::matrix_b, 16, 16, 16, __half, wmma::row_major> bf[2];
#pragma unroll
            for (int i = 0; i < 4; i++)
                wmma::load_matrix_sync(af[i], &As[buf][kk][wm * 64 + i * 16], 136);
#pragma unroll
            for (int j = 0; j < 2; j++)
                wmma::load_matrix_sync(bf[j], &Bs[buf][kk][wn * 32 + j * 16], 136);
#pragma unroll
            for (int i = 0; i < 4; i++)
#pragma unroll
                for (int j = 0; j < 2; j++)
                    wmma::mma_sync(acc[i][j], af[i], bf[j], acc[i][j]);
        }
        __syncthreads();
    }

#pragma unroll 1
    for (int i = 0; i < 4; i++) {
#pragma unroll 1
        for (int j = 0; j < 2; j++) {
            wmma::store_matrix_sync(&wbuf[wid][0], acc[i][j], 16, wmma::mem_row_major);
            __syncwarp();
            const int tm0 = m0 + wm * 64 + i * 16;
            const int tn0 = n0 + wn * 32 + j * 16;
            const int row = lane >> 1;
            const int cb  = (lane & 1) * 8;
            const int p   = tm0 + row;
            float v[8];
#pragma unroll
            for (int c = 0; c < 8; c++) v[c] = wbuf[wid][row * 16 + cb + c];
            float c2[4];
#pragma unroll
            for (int u = 0; u < 4; u++) c2[u] = fmaxf(v[2 * u], v[2 * u + 1]);
#pragma unroll
            for (int u = 0; u < 4; u++)
                c2[u] = fmaxf(c2[u], __shfl_xor_sync(0xffffffffu, c2[u], 2));
            if ((lane & 2) == 0) {
                const int PA = ((p / 48) >> 1) * 24 + ((p % 48) >> 1);
                float* poolb = g_pool + (size_t)b * S + (size_t)PA * PI;
#pragma unroll
                for (int u = 0; u < 4; u++) {
                    int q  = tn0 + cb + 2 * u;
                    int PB = ((q / 48) >> 1) * 24 + ((q % 48) >> 1);
                    atomicMax(reinterpret_cast<int*>(&poolb[PB]), __float_as_int(c2[u]));
                }
            }
            __syncwarp();
        }
    }
}

// ---------------- mutual matching ----------------
__global__ void rowmax_kernel(int which) {
    const float* x = (which == 0) ? g_pool : g_y3;
    int row  = blockIdx.x * 8 + (threadIdx.x >> 5);
    int lane = threadIdx.x & 31;
    const float* xr = x + (size_t)row * PI;
    float m = 0.f;
    for (int j = lane; j < PI; j += 32) m = fmaxf(m, xr[j]);
#pragma unroll
    for (int o = 16; o; o >>= 1) m = fmaxf(m, __shfl_xor_sync(0xffffffffu, m, o));
    if (lane == 0) g_rmax[row] = m;
}

__global__ void colmax_kernel(int which) {  // grid (8,16), 576 thr
    const float* x = (which == 0) ? g_pool : g_y3;
    int b = blockIdx.x, j = threadIdx.x;
    const float* xb = x + (size_t)b * S;
    int i0 = blockIdx.y * 36;
    float m = 0.f;
    for (int i = i0; i < i0 + 36; i++) m = fmaxf(m, xb[(size_t)i * PI + j]);
    atomicMax(reinterpret_cast<int*>(&g_cmax[b * PI + j]), __float_as_int(m));
}

__global__ void mm_apply_kernel(int which, float* __restrict__ outp) {
    int idx = blockIdx.x * blockDim.x + threadIdx.x;
    int b = idx / S, rem = idx - b * S;
    int i = rem / PI, j = rem - i * PI;
    float v  = which ? g_y3[idx] : g_pool[idx];
    float rm = g_rmax[b * PI + i];
    float cm = g_cmax[b * PI + j];
    if (which == 0) {  // deferred x/sqrt(x^2+eps); monotone so maxes transform too
        v  = v  * rsqrtf(v  * v  + EPS_L2);
        rm = rm * rsqrtf(rm * rm + EPS_L2);
        cm = cm * rsqrtf(cm * cm + EPS_L2);
    }
    float* dst = which ? outp : g_x0;
    dst[idx] = v * (v / (rm + EPS_MM)) * (v / (cm + EPS_MM));
}

// ---------------- Conv4d 3^4 SAME, fp32x2 packed FMA, 4 outputs/thread -------
template <int CI, int CO>
__global__ void __launch_bounds__(256)
conv_kernel(const float* __restrict__ x, float* __restrict__ y,
            const float* __restrict__ w, const float* __restrict__ bias) {
    extern __shared__ __align__(16) char dsm[];
    float2* ws2 = reinterpret_cast<float2*>(dsm);  // duplicated weight pairs
    __shared__ float bs[CO];
    for (int l = threadIdx.x; l < 81 * CI * CO; l += 256) {
        int tap = l / (CI * CO), r = l - tap * (CI * CO);
        int ci = r / CO, co = r - ci * CO;
        float wv = w[(co * CI + ci) * 81 + tap];
        ws2[l] = make_float2(wv, wv);
    }
    if (threadIdx.x < CO) bs[threadIdx.x] = bias[threadIdx.x];
    __syncthreads();

    int g = blockIdx.x * 256 + threadIdx.x;           // [0, BATCH*S/4)
    int b = g / (S / 4), r = g - b * (S / 4);
    int d4b = (r % 6) * 4; int r2 = r / 6;
    int d3 = r2 % 24; r2 /= 24;
    int d2 = r2 % 24; int d1 = r2 / 24;
    int s0 = ((d1 * 24 + d2) * 24 + d3) * 24 + d4b;
    const float* xb = x + (size_t)b * CI * S;

    unsigned long long acc[2][CO];
#pragma unroll
    for (int h = 0; h < 2; h++)
#pragma unroll
        for (int co = 0; co < CO; co++) acc[h][co] = 0ull;

#pragma unroll 1
    for (int t1 = 0; t1 < 3; t1++) {
        int e1 = d1 + t1 - 1; if ((unsigned)e1 >= 24u) continue;
#pragma unroll 1
        for (int t2 = 0; t2 < 3; t2++) {
            int e2 = d2 + t2 - 1; if ((unsigned)e2 >= 24u) continue;
#pragma unroll 1
            for (int t3 = 0; t3 < 3; t3++) {
                int e3 = d3 + t3 - 1; if ((unsigned)e3 >= 24u) continue;
                int spb  = ((e1 * 24 + e2) * 24 + e3) * 24 + d4b;
                int tap3 = ((t1 * 3 + t2) * 3 + t3) * 3;
#pragma unroll
                for (int ci = 0; ci < CI; ci++) {
                    float xv[6];
#pragma unroll
                    for (int u = 0; u < 6; u++) {
                        int e4 = d4b + u - 1;
                        xv[u] = ((unsigned)e4 < 24u) ? xb[(size_t)ci * S + spb + u - 1] : 0.f;
                    }
#pragma unroll
                    for (int t4 = 0; t4 < 3; t4++) {
                        unsigned long long xp0 = pack2(xv[t4],     xv[t4 + 1]);
                        unsigned long long xp1 = pack2(xv[t4 + 2], xv[t4 + 3]);
                        const unsigned long long* wq =
                            reinterpret_cast<const unsigned long long*>(
                                ws2 + ((tap3 + t4) * CI + ci) * CO);
#pragma unroll
                        for (int co = 0; co < CO; co++) {
                            unsigned long long wv = wq[co];
                            fma2(acc[0][co], xp0, wv);
                            fma2(acc[1][co], xp1, wv);
                        }
                    }
                }
            }
        }
    }
#pragma unroll
    for (int co = 0; co < CO; co++) {
        float a0, a1, a2, a3;
        unpack2(acc[0][co], a0, a1);
        unpack2(acc[1][co], a2, a3);
        float bb = bs[co];
        float4 o;
        o.x = fmaxf(a0 + bb, 0.f);
        o.y = fmaxf(a1 + bb, 0.f);
        o.z = fmaxf(a2 + bb, 0.f);
        o.w = fmaxf(a3 + bb, 0.f);
        *reinterpret_cast<float4*>(&y[((size_t)b * CO + co) * S + s0]) = o;
    }
}

extern "C" void kernel_launch(void* const* d_in, const int* in_sizes, int n_in,
                              void* d_out, int out_size) {
    const float* fa = (const float*)d_in[0];
    const float* fb = (const float*)d_in[1];
    const float* w1 = (const float*)d_in[2];
    const float* b1 = (const float*)d_in[3];
    const float* w2 = (const float*)d_in[4];
    const float* b2 = (const float*)d_in[5];
    const float* w3 = (const float*)d_in[6];
    const float* b3 = (const float*)d_in[7];
    float* out = (float*)d_out;

    float *p_x0, *p_y1, *p_y2, *p_y3;
    __half *p_fah, *p_fbh;
    cudaGetSymbolAddress((void**)&p_x0, g_x0);
    cudaGetSymbolAddress((void**)&p_y1, g_y1);
    cudaGetSymbolAddress((void**)&p_y2, g_y2);
    cudaGetSymbolAddress((void**)&p_y3, g_y3);
    cudaGetSymbolAddress((void**)&p_fah, g_fah);
    cudaGetSymbolAddress((void**)&p_fbh, g_fbh);

    cudaFuncSetAttribute(conv_kernel<10, 10>, cudaFuncAttributeMaxDynamicSharedMemorySize,
                         81 * 100 * (int)sizeof(float2));

    const int NS = BATCH * S / 256;       // 10368
    const int NG = BATCH * (S / 4) / 256; // 2592
    const size_t NH4 = (size_t)BATCH * CH * P / 4;
    // order: corr is the 4th launch (profiler slot)
    zero_pool_kernel<<<NS, 256>>>();
    norm_kernel<<<BATCH * P / 256, 256>>>(fa, fb);
    scale_half_kernel<<<(unsigned)((NH4 + 255) / 256), 256>>>(fa, fb);
    corr_kernel<<<dim3(18, 18, 8), 256>>>(p_fah, p_fbh);

    rowmax_kernel<<<BATCH * PI / 8, 256>>>(0);
    colmax_kernel<<<dim3(8, 16), PI>>>(0);
    mm_apply_kernel<<<NS, 256>>>(0, nullptr);

    conv_kernel<1, 10><<<NG, 256, 81 * 10 * sizeof(float2)>>>(p_x0, p_y1, w1, b1);
    conv_kernel<10, 10><<<NG, 256, 81 * 100 * sizeof(float2)>>>(p_y1, p_y2, w2, b2);
    conv_kernel<10, 1><<<NG, 256, 81 * 10 * sizeof(float2)>>>(p_y2, p_y3, w3, b3);

    zero_cmax_kernel<<<(BATCH * PI + 255) / 256, 256>>>();
    rowmax_kernel<<<BATCH * PI / 8, 256>>>(1);
    colmax_kernel<<<dim3(8, 16), PI>>>(1);
    mm_apply_kernel<<<NS, 256>>>(1, out);
}

// round 9
// speedup vs baseline: 1.8576x; 1.0214x over previous
#include <cuda_runtime.h>
#include <cuda_pipeline.h>
#include <cuda_fp16.h>
#include <mma.h>
#include <cstdint>

using namespace nvcuda;

namespace {
constexpr int BATCH = 8;
constexpr int CH    = 1024;
constexpr int P     = 48 * 48;     // 2304
constexpr int PD    = 24;
constexpr int PI    = PD * PD;     // 576
constexpr int S     = PI * PI;     // 331776
constexpr float EPS_L2 = 1e-6f;
constexpr float EPS_MM = 1e-5f;
}

__device__ float  g_inva[BATCH * P];
__device__ float  g_invb[BATCH * P];
__device__ __half g_fah[(size_t)BATCH * CH * P];  // scaled fp16 A, [b][k][p]
__device__ __half g_fbh[(size_t)BATCH * CH * P];  // scaled fp16 B, [b][k][p]
__device__ float  g_pool[(size_t)BATCH * S];
__device__ float  g_x0  [(size_t)BATCH * S];
__device__ float  g_y1  [(size_t)BATCH * 10 * S];
__device__ float  g_y2  [(size_t)BATCH * 10 * S];
__device__ float  g_y3  [(size_t)BATCH * S];
__device__ float  g_rmax[BATCH * PI];
__device__ float  g_cmax[BATCH * PI];

// ---------------- f32x2 packed helpers (convs) ----------------
__device__ __forceinline__ void fma2(unsigned long long& d, unsigned long long a,
                                     unsigned long long b) {
    asm("fma.rn.f32x2 %0, %1, %2, %0;" : "+l"(d) : "l"(a), "l"(b));
}
__device__ __forceinline__ unsigned long long pack2(float lo, float hi) {
    unsigned long long r;
    asm("mov.b64 %0, {%1, %2};" : "=l"(r) : "f"(lo), "f"(hi));
    return r;
}
__device__ __forceinline__ void unpack2(unsigned long long v, float& lo, float& hi) {
    asm("mov.b64 {%0, %1}, %2;" : "=f"(lo), "=f"(hi) : "l"(v));
}

// ---------------- per-position inverse L2 norms ----------------
__global__ void norm_kernel(const float* __restrict__ fa, const float* __restrict__ fb) {
    int idx = blockIdx.x * blockDim.x + threadIdx.x;
    int b = idx / P, p = idx - b * P;
    const float* a  = fa + (size_t)b * CH * P + p;
    const float* bb = fb + (size_t)b * CH * P + p;
    float sa = 0.f, sb = 0.f;
#pragma unroll 8
    for (int c = 0; c < CH; c++) {
        float x = a[(size_t)c * P];  sa = fmaf(x, x, sa);
        float y = bb[(size_t)c * P]; sb = fmaf(y, y, sb);
    }
    g_inva[idx] = rsqrtf(sa + EPS_L2);
    g_invb[idx] = rsqrtf(sb + EPS_L2);
}

__global__ void zero_pool_kernel() {
    size_t i = (size_t)blockIdx.x * blockDim.x + threadIdx.x;
    g_pool[i] = 0.f;
    if (i < BATCH * PI) g_cmax[i] = 0.f;
}
__global__ void zero_cmax_kernel() {
    int i = blockIdx.x * blockDim.x + threadIdx.x;
    if (i < BATCH * PI) g_cmax[i] = 0.f;
}

// ---- scale-by-invnorm + fp16 convert, layout preserved [b][k][p] ----
__global__ void scale_half_kernel(const float* __restrict__ fa,
                                  const float* __restrict__ fb) {
    size_t i4 = (size_t)blockIdx.x * blockDim.x + threadIdx.x;   // 4 elements each
    size_t i  = i4 * 4;
    if (i >= (size_t)BATCH * CH * P) return;
    int b  = (int)(i / ((size_t)CH * P));
    int p  = (int)(i % P);
    const float4 a4 = *reinterpret_cast<const float4*>(fa + i);
    const float4 b4 = *reinterpret_cast<const float4*>(fb + i);
    const float* ia = g_inva + b * P + p;
    const float* ib = g_invb + b * P + p;
    __half2 ha0 = __floats2half2_rn(a4.x * ia[0], a4.y * ia[1]);
    __half2 ha1 = __floats2half2_rn(a4.z * ia[2], a4.w * ia[3]);
    __half2 hb0 = __floats2half2_rn(b4.x * ib[0], b4.y * ib[1]);
    __half2 hb1 = __floats2half2_rn(b4.z * ib[2], b4.w * ib[3]);
    *reinterpret_cast<__half2*>(&g_fah[i])     = ha0;
    *reinterpret_cast<__half2*>(&g_fah[i + 2]) = ha1;
    *reinterpret_cast<__half2*>(&g_fbh[i])     = hb0;
    *reinterpret_cast<__half2*>(&g_fbh[i + 2]) = hb1;
}

// ---- correlation GEMM (fp16 wmma m16n16k16, 128x128 block, 64x32 warp) ----
// __launch_bounds__(256, 2): cap 128 regs so 2 CTAs co-reside per SM (R8 had
// 146 regs -> 1 CTA -> issue 7.3%; this is the occupancy fix).
__global__ void __launch_bounds__(256, 2)
corr_kernel(const __half* __restrict__ fah, const __half* __restrict__ fbh) {
    __shared__ __align__(16) __half As[2][32][136];
    __shared__ __align__(16) __half Bs[2][32][136];
    __shared__ float wbuf[8][256];

    const int b  = blockIdx.z;
    const __half* Ag = fah + (size_t)b * CH * P;
    const __half* Bg = fbh + (size_t)b * CH * P;
    const int m0 = blockIdx.x * 128, n0 = blockIdx.y * 128;
    const int tid = threadIdx.x, wid = tid >> 5, lane = tid & 31;
    const int wm = wid >> 2, wn = wid & 3;   // 64(m) x 32(n) per warp

    wmma::fragment<wmma::accumulator, 16, 16, 16, float> acc[4][2];
#pragma unroll
    for (int i = 0; i < 4; i++)
#pragma unroll
        for (int j = 0; j < 2; j++) wmma::fill_fragment(acc[i][j], 0.0f);

    auto load_tile = [&](int kt, int buf) {
        const int k0 = kt * 32;
#pragma unroll
        for (int v = 0; v < 2; v++) {
            int l = v * 256 + tid;              // 0..511
            int r = l >> 4, c = (l & 15) * 8;   // row k, 8-half chunk
            __pipeline_memcpy_async(&As[buf][r][c], Ag + (size_t)(k0 + r) * P + m0 + c, 16);
            __pipeline_memcpy_async(&Bs[buf][r][c], Bg + (size_t)(k0 + r) * P + n0 + c, 16);
        }
        __pipeline_commit();
    };

    load_tile(0, 0);
    const int NT = CH / 32;   // 32
    for (int kt = 0; kt < NT; kt++) {
        if (kt + 1 < NT) load_tile(kt + 1, (kt + 1) & 1);
        __pipeline_wait_prior((kt + 1 < NT) ? 1 : 0);
        __syncthreads();
        const int buf = kt & 1;
#pragma unroll
        for (int ks = 0; ks < 2; ks++) {
            const int kk = ks * 16;
            wmma::fragment<wmma::matrix_a, 16, 16, 16, __half, wmma::col_major> af[4];
            wmma::fragment<wmma::matrix_b, 16, 16, 16, __half, wmma::row_major> bf[2];
#pragma unroll
            for (int i = 0; i < 4; i++)
                wmma::load_matrix_sync(af[i], &As[buf][kk][wm * 64 + i * 16], 136);
#pragma unroll
            for (int j = 0; j < 2; j++)
                wmma::load_matrix_sync(bf[j], &Bs[buf][kk][wn * 32 + j * 16], 136);
#pragma unroll
            for (int i = 0; i < 4; i++)
#pragma unroll
                for (int j = 0; j < 2; j++)
                    wmma::mma_sync(acc[i][j], af[i], bf[j], acc[i][j]);
        }
        __syncthreads();
    }

#pragma unroll 1
    for (int i = 0; i < 4; i++) {
#pragma unroll 1
        for (int j = 0; j < 2; j++) {
            wmma::store_matrix_sync(&wbuf[wid][0], acc[i][j], 16, wmma::mem_row_major);
            __syncwarp();
            const int tm0 = m0 + wm * 64 + i * 16;
            const int tn0 = n0 + wn * 32 + j * 16;
            const int row = lane >> 1;
            const int cb  = (lane & 1) * 8;
            const int p   = tm0 + row;
            float v[8];
#pragma unroll
            for (int c = 0; c < 8; c++) v[c] = wbuf[wid][row * 16 + cb + c];
            float c2[4];
#pragma unroll
            for (int u = 0; u < 4; u++) c2[u] = fmaxf(v[2 * u], v[2 * u + 1]);
#pragma unroll
            for (int u = 0; u < 4; u++)
                c2[u] = fmaxf(c2[u], __shfl_xor_sync(0xffffffffu, c2[u], 2));
            if ((lane & 2) == 0) {
                const int PA = ((p / 48) >> 1) * 24 + ((p % 48) >> 1);
                float* poolb = g_pool + (size_t)b * S + (size_t)PA * PI;
#pragma unroll
                for (int u = 0; u < 4; u++) {
                    int q  = tn0 + cb + 2 * u;
                    int PB = ((q / 48) >> 1) * 24 + ((q % 48) >> 1);
                    atomicMax(reinterpret_cast<int*>(&poolb[PB]), __float_as_int(c2[u]));
                }
            }
            __syncwarp();
        }
    }
}

// ---------------- mutual matching ----------------
__global__ void rowmax_kernel(int which) {
    const float* x = (which == 0) ? g_pool : g_y3;
    int row  = blockIdx.x * 8 + (threadIdx.x >> 5);
    int lane = threadIdx.x & 31;
    const float* xr = x + (size_t)row * PI;
    float m = 0.f;
    for (int j = lane; j < PI; j += 32) m = fmaxf(m, xr[j]);
#pragma unroll
    for (int o = 16; o; o >>= 1) m = fmaxf(m, __shfl_xor_sync(0xffffffffu, m, o));
    if (lane == 0) g_rmax[row] = m;
}

__global__ void colmax_kernel(int which) {  // grid (8,16), 576 thr
    const float* x = (which == 0) ? g_pool : g_y3;
    int b = blockIdx.x, j = threadIdx.x;
    const float* xb = x + (size_t)b * S;
    int i0 = blockIdx.y * 36;
    float m = 0.f;
    for (int i = i0; i < i0 + 36; i++) m = fmaxf(m, xb[(size_t)i * PI + j]);
    atomicMax(reinterpret_cast<int*>(&g_cmax[b * PI + j]), __float_as_int(m));
}

__global__ void mm_apply_kernel(int which, float* __restrict__ outp) {
    int idx = blockIdx.x * blockDim.x + threadIdx.x;
    int b = idx / S, rem = idx - b * S;
    int i = rem / PI, j = rem - i * PI;
    float v  = which ? g_y3[idx] : g_pool[idx];
    float rm = g_rmax[b * PI + i];
    float cm = g_cmax[b * PI + j];
    if (which == 0) {  // deferred x/sqrt(x^2+eps); monotone so maxes transform too
        v  = v  * rsqrtf(v  * v  + EPS_L2);
        rm = rm * rsqrtf(rm * rm + EPS_L2);
        cm = cm * rsqrtf(cm * cm + EPS_L2);
    }
    float* dst = which ? outp : g_x0;
    dst[idx] = v * (v / (rm + EPS_MM)) * (v / (cm + EPS_MM));
}

// ---------------- Conv4d 3^4 SAME, fp32x2 packed FMA, 4 outputs/thread -------
template <int CI, int CO>
__global__ void __launch_bounds__(256)
conv_kernel(const float* __restrict__ x, float* __restrict__ y,
            const float* __restrict__ w, const float* __restrict__ bias) {
    extern __shared__ __align__(16) char dsm[];
    float2* ws2 = reinterpret_cast<float2*>(dsm);  // duplicated weight pairs
    __shared__ float bs[CO];
    for (int l = threadIdx.x; l < 81 * CI * CO; l += 256) {
        int tap = l / (CI * CO), r = l - tap * (CI * CO);
        int ci = r / CO, co = r - ci * CO;
        float wv = w[(co * CI + ci) * 81 + tap];
        ws2[l] = make_float2(wv, wv);
    }
    if (threadIdx.x < CO) bs[threadIdx.x] = bias[threadIdx.x];
    __syncthreads();

    int g = blockIdx.x * 256 + threadIdx.x;           // [0, BATCH*S/4)
    int b = g / (S / 4), r = g - b * (S / 4);
    int d4b = (r % 6) * 4; int r2 = r / 6;
    int d3 = r2 % 24; r2 /= 24;
    int d2 = r2 % 24; int d1 = r2 / 24;
    int s0 = ((d1 * 24 + d2) * 24 + d3) * 24 + d4b;
    const float* xb = x + (size_t)b * CI * S;

    unsigned long long acc[2][CO];
#pragma unroll
    for (int h = 0; h < 2; h++)
#pragma unroll
        for (int co = 0; co < CO; co++) acc[h][co] = 0ull;

#pragma unroll 1
    for (int t1 = 0; t1 < 3; t1++) {
        int e1 = d1 + t1 - 1; if ((unsigned)e1 >= 24u) continue;
#pragma unroll 1
        for (int t2 = 0; t2 < 3; t2++) {
            int e2 = d2 + t2 - 1; if ((unsigned)e2 >= 24u) continue;
#pragma unroll 1
            for (int t3 = 0; t3 < 3; t3++) {
                int e3 = d3 + t3 - 1; if ((unsigned)e3 >= 24u) continue;
                int spb  = ((e1 * 24 + e2) * 24 + e3) * 24 + d4b;
                int tap3 = ((t1 * 3 + t2) * 3 + t3) * 3;
#pragma unroll
                for (int ci = 0; ci < CI; ci++) {
                    float xv[6];
#pragma unroll
                    for (int u = 0; u < 6; u++) {
                        int e4 = d4b + u - 1;
                        xv[u] = ((unsigned)e4 < 24u) ? xb[(size_t)ci * S + spb + u - 1] : 0.f;
                    }
#pragma unroll
                    for (int t4 = 0; t4 < 3; t4++) {
                        unsigned long long xp0 = pack2(xv[t4],     xv[t4 + 1]);
                        unsigned long long xp1 = pack2(xv[t4 + 2], xv[t4 + 3]);
                        const unsigned long long* wq =
                            reinterpret_cast<const unsigned long long*>(
                                ws2 + ((tap3 + t4) * CI + ci) * CO);
#pragma unroll
                        for (int co = 0; co < CO; co++) {
                            unsigned long long wv = wq[co];
                            fma2(acc[0][co], xp0, wv);
                            fma2(acc[1][co], xp1, wv);
                        }
                    }
                }
            }
        }
    }
#pragma unroll
    for (int co = 0; co < CO; co++) {
        float a0, a1, a2, a3;
        unpack2(acc[0][co], a0, a1);
        unpack2(acc[1][co], a2, a3);
        float bb = bs[co];
        float4 o;
        o.x = fmaxf(a0 + bb, 0.f);
        o.y = fmaxf(a1 + bb, 0.f);
        o.z = fmaxf(a2 + bb, 0.f);
        o.w = fmaxf(a3 + bb, 0.f);
        *reinterpret_cast<float4*>(&y[((size_t)b * CO + co) * S + s0]) = o;
    }
}

extern "C" void kernel_launch(void* const* d_in, const int* in_sizes, int n_in,
                              void* d_out, int out_size) {
    const float* fa = (const float*)d_in[0];
    const float* fb = (const float*)d_in[1];
    const float* w1 = (const float*)d_in[2];
    const float* b1 = (const float*)d_in[3];
    const float* w2 = (const float*)d_in[4];
    const float* b2 = (const float*)d_in[5];
    const float* w3 = (const float*)d_in[6];
    const float* b3 = (const float*)d_in[7];
    float* out = (float*)d_out;

    float *p_x0, *p_y1, *p_y2, *p_y3;
    __half *p_fah, *p_fbh;
    cudaGetSymbolAddress((void**)&p_x0, g_x0);
    cudaGetSymbolAddress((void**)&p_y1, g_y1);
    cudaGetSymbolAddress((void**)&p_y2, g_y2);
    cudaGetSymbolAddress((void**)&p_y3, g_y3);
    cudaGetSymbolAddress((void**)&p_fah, g_fah);
    cudaGetSymbolAddress((void**)&p_fbh, g_fbh);

    cudaFuncSetAttribute(conv_kernel<10, 10>, cudaFuncAttributeMaxDynamicSharedMemorySize,
                         81 * 100 * (int)sizeof(float2));

    const int NS = BATCH * S / 256;       // 10368
    const int NG = BATCH * (S / 4) / 256; // 2592
    const size_t NH4 = (size_t)BATCH * CH * P / 4;
    // order: corr is the 4th launch (profiler slot)
    zero_pool_kernel<<<NS, 256>>>();
    norm_kernel<<<BATCH * P / 256, 256>>>(fa, fb);
    scale_half_kernel<<<(unsigned)((NH4 + 255) / 256), 256>>>(fa, fb);
    corr_kernel<<<dim3(18, 18, 8), 256>>>(p_fah, p_fbh);

    rowmax_kernel<<<BATCH * PI / 8, 256>>>(0);
    colmax_kernel<<<dim3(8, 16), PI>>>(0);
    mm_apply_kernel<<<NS, 256>>>(0, nullptr);

    conv_kernel<1, 10><<<NG, 256, 81 * 10 * sizeof(float2)>>>(p_x0, p_y1, w1, b1);
    conv_kernel<10, 10><<<NG, 256, 81 * 100 * sizeof(float2)>>>(p_y1, p_y2, w2, b2);
    conv_kernel<10, 1><<<NG, 256, 81 * 10 * sizeof(float2)>>>(p_y2, p_y3, w3, b3);

    zero_cmax_kernel<<<(BATCH * PI + 255) / 256, 256>>>();
    rowmax_kernel<<<BATCH * PI / 8, 256>>>(1);
    colmax_kernel<<<dim3(8, 16), PI>>>(1);
    mm_apply_kernel<<<NS, 256>>>(1, out);
}